// round 11
// baseline (speedup 1.0000x reference)
#include <cuda_runtime.h>
#include <cuda_fp16.h>
#include <math.h>
#include <stdint.h>

#define BATCH   8192
#define DIM     256
#define KRED    1024
#define NCOEF   5
#define NLAYERS 2
#define LN_EPS  1e-6f

// ---------------------------------------------------------------------------
// Scratch
// ---------------------------------------------------------------------------
__device__ float  g_h [BATCH * DIM];
__device__ __half g_Bn[NLAYERS * DIM * KRED];
__device__ float  g_bias[NLAYERS * DIM];
__device__ float  g_jc[NLAYERS * 8];   // p1c, bb0, bb1, bb2, cc0, cc1, cc2, pad

// ---------------------------------------------------------------------------
// Helpers
// ---------------------------------------------------------------------------
__device__ __forceinline__ uint32_t smem_u32(const void* p) {
    uint32_t a;
    asm("{ .reg .u64 t; cvta.to.shared.u64 t, %1; cvt.u32.u64 %0, t; }"
        : "=r"(a) : "l"(p));
    return a;
}
__device__ __forceinline__ void mma_f16_16n8k16(float* d, const uint32_t* a,
                                                const uint32_t* b) {
    asm volatile(
        "mma.sync.aligned.m16n8k16.row.col.f32.f16.f16.f32 "
        "{%0,%1,%2,%3}, {%4,%5,%6,%7}, {%8,%9}, {%0,%1,%2,%3};"
        : "+f"(d[0]), "+f"(d[1]), "+f"(d[2]), "+f"(d[3])
        : "r"(a[0]), "r"(a[1]), "r"(a[2]), "r"(a[3]),
          "r"(b[0]), "r"(b[1]));
}
#define LDSM4(r0, r1, r2, r3, addr) \
    asm volatile("ldmatrix.sync.aligned.m8n8.x4.shared.b16 {%0,%1,%2,%3}, [%4];" \
        : "=r"(r0), "=r"(r1), "=r"(r2), "=r"(r3) : "r"(addr))
#define CP_ASYNC16(dst, src) \
    asm volatile("cp.async.ca.shared.global [%0], [%1], 16;" \
        :: "r"(dst), "l"(src))
#define CP_COMMIT()  asm volatile("cp.async.commit_group;" ::: "memory")
#define CP_WAIT1()   asm volatile("cp.async.wait_group 1;"  ::: "memory")

// ---------------------------------------------------------------------------
// build Bn[l][o][k], k = i*4 + (c-1), fp16
// ---------------------------------------------------------------------------
__global__ void build_Bn(const float* __restrict__ coefs,
                         __half* __restrict__ Bn) {
    int idx = blockIdx.x * blockDim.x + threadIdx.x;
    const int total = NLAYERS * DIM * KRED;
    if (idx >= total) return;
    int k = idx & (KRED - 1);
    int o = (idx >> 10) & (DIM - 1);
    int l = idx >> 18;
    int i = k >> 2;
    int c = (k & 3) + 1;
    Bn[idx] = __float2half_rn(
        coefs[(((size_t)(l * DIM + i)) * DIM + o) * NCOEF + c]);
}

// ---------------------------------------------------------------------------
// bias[l][o] = sum_i coefs[l][i][o][0]; also Jacobi coefficient table
// ---------------------------------------------------------------------------
__global__ void __launch_bounds__(128)
build_bias(const float* __restrict__ coefs, const float* __restrict__ alphas,
           float* __restrict__ bias, float* __restrict__ jc) {
    int lo = blockIdx.x;
    int l = lo >> 8, o = lo & 255;
    float s = 0.0f;
    for (int i = threadIdx.x; i < DIM; i += 128)
        s += coefs[(((size_t)(l * DIM + i)) * DIM + o) * NCOEF];
    #pragma unroll
    for (int off = 16; off; off >>= 1) s += __shfl_xor_sync(0xFFFFFFFFu, s, off);
    __shared__ float red[4];
    if ((threadIdx.x & 31) == 0) red[threadIdx.x >> 5] = s;
    __syncthreads();
    if (threadIdx.x == 0)
        bias[lo] = red[0] + red[1] + red[2] + red[3];

    if (o == 0 && threadIdx.x == 0) {
        float a = tanhf(alphas[l]);
        jc[l * 8 + 0] = a + 1.0f;
        #pragma unroll
        for (int k = 2; k <= 4; k++) {
            float kf = (float)k;
            float t  = 2.0f * kf + 2.0f * a;
            float A  = 2.0f * kf * (kf + 2.0f * a) * (t - 2.0f);
            float B  = (t - 1.0f) * t * (t - 2.0f);
            float Cc = 2.0f * (kf + a - 1.0f) * (kf + a - 1.0f) * t;
            jc[l * 8 + (k - 1)] = B / A;       // bb[k-2] at idx 1..3
            jc[l * 8 + 3 + (k - 1)] = Cc / A;  // cc[k-2] at idx 4..6
        }
        jc[l * 8 + 7] = 0.0f;
    }
}

// ---------------------------------------------------------------------------
// Fused layer: LN + tanh + Jacobi A-gen + fp16 HMMA GEMM.
// CTA tile 64(M) x 128(N), BK=128 (32 input dims/chunk), 256 threads, 8 warps
// (2m x 4n, 32x32 warp tiles). 2-stage B ring, 2 A buffers, 2 CTAs/SM.
// ---------------------------------------------------------------------------
#define BK        128
#define NCHUNK    (KRED / BK)         // 8
#define ROWB      272                 // 256 + 16 pad
#define A_TILE_B  (64 * ROWB)         // 17408
#define B_TILE_B  (128 * ROWB)        // 34816
#define SM_A      1024
#define SM_B      (1024 + 2 * A_TILE_B)          // 35840
#define SMEM_FUSED_BYTES (1024 + 2 * A_TILE_B + 2 * B_TILE_B)  // 105472

__global__ void __launch_bounds__(256, 2)
fused_layer(const float* __restrict__ h,
            const __half* __restrict__ Bn,
            const float* __restrict__ biasP0,
            const float* __restrict__ lnscale,
            const float* __restrict__ lnbias,
            const float* __restrict__ jc,
            float* __restrict__ C) {
    extern __shared__ char sm[];
    const uint32_t sb = smem_u32(sm);
    float2* stats = (float2*)sm;      // 64 rows

    const int tid = threadIdx.x;
    const int lid = tid & 31;
    const int wid = tid >> 5;
    const int warp_m = wid & 1;
    const int warp_n = wid >> 1;
    const int qr = lid >> 2;
    const int qc = lid & 3;

    const int bm = blockIdx.x * 64;
    const int bn = blockIdx.y * 128;

    // B stage loader: 128 rows x 256 B = 2048 x 16B tasks / 256 threads
    auto issueB = [&](int stage, int ch) {
        const uint32_t st = sb + SM_B + (uint32_t)stage * B_TILE_B;
        #pragma unroll
        for (int it = 0; it < 8; it++) {
            int idx = tid + it * 256;
            int row = idx >> 4, q16 = idx & 15;
            const __half* gb = Bn + (size_t)(bn + row) * KRED + ch * BK + q16 * 8;
            CP_ASYNC16(st + row * ROWB + q16 * 16, gb);
        }
        CP_COMMIT();
    };

    // h prefetch: row r0 = tid>>2, two float4 at cols i4*4 and 16+i4*4
    const int i4 = tid & 3;
    const int r0 = tid >> 2;
    auto loadH = [&](int ch, float4& v0, float4& v1) {
        const float* g = h + (size_t)(bm + r0) * DIM + ch * 32;
        v0 = *(const float4*)(g + i4 * 4);
        v1 = *(const float4*)(g + 16 + i4 * 4);
    };

    // A generation: row r0, 8 input dims -> 32 halves (64 B)
    auto genA = [&](int ch, int abuf, float4 v0, float4 v1) {
        float4 j0 = __ldg((const float4*)jc);       // p1c, bb0, bb1, bb2
        float4 j1 = __ldg((const float4*)jc + 1);   // cc0, cc1, cc2, -
        float2 st = stats[r0];
        char* abase = sm + SM_A + abuf * A_TILE_B + r0 * ROWB;
        #pragma unroll
        for (int g = 0; g < 2; g++) {
            int cbase = ch * 32 + g * 16 + i4 * 4;
            float4 sc = *(const float4*)(lnscale + cbase);
            float4 bi = *(const float4*)(lnbias  + cbase);
            float4 v = g ? v1 : v0;
            float xv[4]  = {v.x, v.y, v.z, v.w};
            float scv[4] = {sc.x, sc.y, sc.z, sc.w};
            float biv[4] = {bi.x, bi.y, bi.z, bi.w};
            uint32_t oh[8];
            #pragma unroll
            for (int e = 0; e < 4; e++) {
                float x  = tanhf((xv[e] - st.x) * st.y * scv[e] + biv[e]);
                float P1 = j0.x * x;
                float P2 = j0.y * x * P1 - j1.x;
                float P3 = j0.z * x * P2 - j1.y * P1;
                float P4 = j0.w * x * P3 - j1.z * P2;
                __half2 h0 = __floats2half2_rn(P1, P2);
                __half2 h1 = __floats2half2_rn(P3, P4);
                oh[2 * e]     = *(uint32_t*)&h0;
                oh[2 * e + 1] = *(uint32_t*)&h1;
            }
            uint4* dst = (uint4*)(abase + g * 128 + i4 * 32);
            dst[0] = make_uint4(oh[0], oh[1], oh[2], oh[3]);
            dst[1] = make_uint4(oh[4], oh[5], oh[6], oh[7]);
        }
    };

    // -------- prologue ------------------------------------------------------
    issueB(0, 0);
    issueB(1, 1);

    {   // LN stats: warp w -> rows w*8 .. w*8+7
        #pragma unroll 1
        for (int j = 0; j < 8; j++) {
            int row = wid * 8 + j;
            const float4* p = (const float4*)(h + (size_t)(bm + row) * DIM) + lid * 2;
            float4 u = p[0], v = p[1];
            float s  = u.x + u.y + u.z + u.w + v.x + v.y + v.z + v.w;
            float s2 = u.x*u.x + u.y*u.y + u.z*u.z + u.w*u.w
                     + v.x*v.x + v.y*v.y + v.z*v.z + v.w*v.w;
            #pragma unroll
            for (int off = 16; off; off >>= 1) {
                s  += __shfl_xor_sync(0xFFFFFFFFu, s,  off);
                s2 += __shfl_xor_sync(0xFFFFFFFFu, s2, off);
            }
            if (lid == 0) {
                float mu  = s * (1.0f / DIM);
                float var = s2 * (1.0f / DIM) - mu * mu;
                stats[row] = make_float2(mu, rsqrtf(var + LN_EPS));
            }
        }
    }
    __syncthreads();              // stats visible

    float4 ha0, ha1, hb0, hb1;
    loadH(0, ha0, ha1);
    genA(0, 0, ha0, ha1);
    loadH(1, hb0, hb1);

    CP_WAIT1();                   // B(0) arrived (own copies)
    __syncthreads();              // A(0) + B(0) visible to all

    // ldmatrix lane offsets
    const uint32_t a_loff =
        (uint32_t)((warp_m * 32 + (lid & 15)) * ROWB + ((lid >> 4) << 4));
    const uint32_t b_loff =
        (uint32_t)((warp_n * 32 + ((lid & 7) | ((lid >> 4) << 3))) * ROWB +
                   (((lid >> 3) & 1) << 4));

    float acc[2][4][4];
    #pragma unroll
    for (int mt = 0; mt < 2; mt++)
        #pragma unroll
        for (int nt = 0; nt < 4; nt++)
            #pragma unroll
            for (int j = 0; j < 4; j++) acc[mt][nt][j] = 0.0f;

    #pragma unroll 1
    for (int c = 0; c < NCHUNK; c++) {
        const uint32_t stA = sb + SM_A + (uint32_t)(c & 1) * A_TILE_B;
        const uint32_t stB = sb + SM_B + (uint32_t)(c & 1) * B_TILE_B;

        #pragma unroll
        for (int ks = 0; ks < 8; ks++) {        // 8 x k16 per BK=128
            uint32_t af[2][4], bf[4][2];
            #pragma unroll
            for (int mt = 0; mt < 2; mt++)
                LDSM4(af[mt][0], af[mt][1], af[mt][2], af[mt][3],
                      stA + a_loff + (uint32_t)(mt * 16 * ROWB + ks * 32));
            #pragma unroll
            for (int p = 0; p < 2; p++)
                LDSM4(bf[2*p][0], bf[2*p][1], bf[2*p+1][0], bf[2*p+1][1],
                      stB + b_loff + (uint32_t)(p * 16 * ROWB + ks * 32));
            #pragma unroll
            for (int mt = 0; mt < 2; mt++)
                #pragma unroll
                for (int nt = 0; nt < 4; nt++)
                    mma_f16_16n8k16(acc[mt][nt], af[mt], bf[nt]);
        }

        if (c + 1 < NCHUNK) {
            genA(c + 1, (c + 1) & 1, hb0, hb1);
            if (c + 2 < NCHUNK) loadH(c + 2, hb0, hb1);
            __syncthreads();                 // LDSM(c) done; A(c+1) STS done
            if (c + 2 < NCHUNK) issueB(c & 1, c + 2);
            else CP_COMMIT();
            CP_WAIT1();                      // B(c+1) own copies arrived
            __syncthreads();                 // B(c+1) visible to all
        }
    }

    // -------- epilogue: C = (acc + bias) / DIM ------------------------------
    const float inv = 1.0f / (float)DIM;
    const int re = bm + warp_m * 32 + qr;
    const int ce = bn + warp_n * 32 + qc * 2;
    #pragma unroll
    for (int mt = 0; mt < 2; mt++) {
        #pragma unroll
        for (int nt = 0; nt < 4; nt++) {
            int col = ce + nt * 8;
            float2 bv = *(const float2*)(biasP0 + col);
            int row = re + mt * 16;
            float2 o0, o1;
            o0.x = (acc[mt][nt][0] + bv.x) * inv;
            o0.y = (acc[mt][nt][1] + bv.y) * inv;
            o1.x = (acc[mt][nt][2] + bv.x) * inv;
            o1.y = (acc[mt][nt][3] + bv.y) * inv;
            *(float2*)(C + (size_t)row * DIM + col)       = o0;
            *(float2*)(C + (size_t)(row + 8) * DIM + col) = o1;
        }
    }
}

// ---------------------------------------------------------------------------
// Launch
// ---------------------------------------------------------------------------
extern "C" void kernel_launch(void* const* d_in, const int* in_sizes, int n_in,
                              void* d_out, int out_size) {
    const float* x        = (const float*)d_in[0];
    const float* coefs    = (const float*)d_in[1];
    const float* alphas   = (const float*)d_in[2];
    const float* ln_scale = (const float*)d_in[3];
    const float* ln_bias  = (const float*)d_in[4];
    float* out = (float*)d_out;

    float* hbuf; cudaGetSymbolAddress((void**)&hbuf, g_h);
    __half* Bn;  cudaGetSymbolAddress((void**)&Bn,   g_Bn);
    float* bias; cudaGetSymbolAddress((void**)&bias, g_bias);
    float* jc;   cudaGetSymbolAddress((void**)&jc,   g_jc);

    cudaFuncSetAttribute(fused_layer,
                         cudaFuncAttributeMaxDynamicSharedMemorySize,
                         SMEM_FUSED_BYTES);

    {
        int total = NLAYERS * DIM * KRED;
        build_Bn<<<(total + 255) / 256, 256>>>(coefs, Bn);
        build_bias<<<NLAYERS * DIM, 128>>>(coefs, alphas, bias, jc);
    }

    dim3 ggrid(BATCH / 64, DIM / 128);   // (128, 2) = 256 CTAs

    fused_layer<<<ggrid, 256, SMEM_FUSED_BYTES>>>(
        x, Bn, bias, ln_scale, ln_bias, jc, hbuf);

    fused_layer<<<ggrid, 256, SMEM_FUSED_BYTES>>>(
        hbuf, Bn + (size_t)DIM * KRED, bias + DIM,
        ln_scale + DIM, ln_bias + DIM, jc + 8, out);
}

// round 12
// speedup vs baseline: 1.0385x; 1.0385x over previous
#include <cuda_runtime.h>
#include <cuda_fp16.h>
#include <math.h>
#include <stdint.h>

#define BATCH   8192
#define DIM     256
#define KRED    1024
#define NCOEF   5
#define NLAYERS 2
#define LN_EPS  1e-6f

// ---------------------------------------------------------------------------
// Scratch
// ---------------------------------------------------------------------------
__device__ float  g_h [BATCH * DIM];
__device__ __half g_Bn[NLAYERS * DIM * KRED];
__device__ float  g_bias[NLAYERS * DIM];
__device__ float  g_jc[NLAYERS * 8];   // p1c, bb0, bb1, bb2, cc0, cc1, cc2, pad

// ---------------------------------------------------------------------------
// Helpers
// ---------------------------------------------------------------------------
__device__ __forceinline__ uint32_t smem_u32(const void* p) {
    uint32_t a;
    asm("{ .reg .u64 t; cvta.to.shared.u64 t, %1; cvt.u32.u64 %0, t; }"
        : "=r"(a) : "l"(p));
    return a;
}
__device__ __forceinline__ float tanh_fast(float v) {
    float r;
    asm("tanh.approx.f32 %0, %1;" : "=f"(r) : "f"(v));
    return r;
}
__device__ __forceinline__ void mma_f16_16n8k16(float* d, const uint32_t* a,
                                                const uint32_t* b) {
    asm volatile(
        "mma.sync.aligned.m16n8k16.row.col.f32.f16.f16.f32 "
        "{%0,%1,%2,%3}, {%4,%5,%6,%7}, {%8,%9}, {%0,%1,%2,%3};"
        : "+f"(d[0]), "+f"(d[1]), "+f"(d[2]), "+f"(d[3])
        : "r"(a[0]), "r"(a[1]), "r"(a[2]), "r"(a[3]),
          "r"(b[0]), "r"(b[1]));
}
#define LDSM4(r0, r1, r2, r3, addr) \
    asm volatile("ldmatrix.sync.aligned.m8n8.x4.shared.b16 {%0,%1,%2,%3}, [%4];" \
        : "=r"(r0), "=r"(r1), "=r"(r2), "=r"(r3) : "r"(addr))
#define CP_ASYNC16(dst, src) \
    asm volatile("cp.async.ca.shared.global [%0], [%1], 16;" \
        :: "r"(dst), "l"(src))
#define CP_COMMIT()  asm volatile("cp.async.commit_group;" ::: "memory")
#define CP_WAIT1()   asm volatile("cp.async.wait_group 1;"  ::: "memory")

// ---------------------------------------------------------------------------
// build Bn[l][o][k], k = i*4 + (c-1), fp16
// ---------------------------------------------------------------------------
__global__ void build_Bn(const float* __restrict__ coefs,
                         __half* __restrict__ Bn) {
    int idx = blockIdx.x * blockDim.x + threadIdx.x;
    const int total = NLAYERS * DIM * KRED;
    if (idx >= total) return;
    int k = idx & (KRED - 1);
    int o = (idx >> 10) & (DIM - 1);
    int l = idx >> 18;
    int i = k >> 2;
    int c = (k & 3) + 1;
    Bn[idx] = __float2half_rn(
        coefs[(((size_t)(l * DIM + i)) * DIM + o) * NCOEF + c]);
}

// ---------------------------------------------------------------------------
// bias[l][o] = sum_i coefs[l][i][o][0]; Jacobi coefficient table
// ---------------------------------------------------------------------------
__global__ void __launch_bounds__(128)
build_bias(const float* __restrict__ coefs, const float* __restrict__ alphas,
           float* __restrict__ bias, float* __restrict__ jc) {
    int lo = blockIdx.x;
    int l = lo >> 8, o = lo & 255;
    float s = 0.0f;
    for (int i = threadIdx.x; i < DIM; i += 128)
        s += coefs[(((size_t)(l * DIM + i)) * DIM + o) * NCOEF];
    #pragma unroll
    for (int off = 16; off; off >>= 1) s += __shfl_xor_sync(0xFFFFFFFFu, s, off);
    __shared__ float red[4];
    if ((threadIdx.x & 31) == 0) red[threadIdx.x >> 5] = s;
    __syncthreads();
    if (threadIdx.x == 0)
        bias[lo] = red[0] + red[1] + red[2] + red[3];

    if (o == 0 && threadIdx.x == 0) {
        float a = tanhf(alphas[l]);   // exact; host-grade path, tiny kernel
        jc[l * 8 + 0] = a + 1.0f;
        #pragma unroll
        for (int k = 2; k <= 4; k++) {
            float kf = (float)k;
            float t  = 2.0f * kf + 2.0f * a;
            float A  = 2.0f * kf * (kf + 2.0f * a) * (t - 2.0f);
            float B  = (t - 1.0f) * t * (t - 2.0f);
            float Cc = 2.0f * (kf + a - 1.0f) * (kf + a - 1.0f) * t;
            jc[l * 8 + (k - 1)]     = B / A;
            jc[l * 8 + 3 + (k - 1)] = Cc / A;
        }
        jc[l * 8 + 7] = 0.0f;
    }
}

// ---------------------------------------------------------------------------
// Fused layer: LN + tanh + Jacobi A-gen + fp16 HMMA GEMM.
// CTA tile 64(M) x 128(N), BK=64, 256 threads, 8 warps (2m x 4n, 32x32).
// 3-stage B ring, 2 A buffers, one __syncthreads per chunk.
// 74.75 KB smem, <=84 regs -> 3 CTAs/SM.
// ---------------------------------------------------------------------------
#define BK        64
#define NCHUNK    (KRED / BK)         // 16
#define ROWB      144
#define A_TILE_B  (64 * ROWB)         // 9216
#define B_TILE_B  (128 * ROWB)        // 18432
#define SM_A      1024
#define SM_B      (1024 + 2 * A_TILE_B)   // 19456
#define SMEM_FUSED_BYTES (1024 + 2 * A_TILE_B + 3 * B_TILE_B)  // 74752

__global__ void __launch_bounds__(256, 3)
fused_layer(const float* __restrict__ h,
            const __half* __restrict__ Bn,
            const float* __restrict__ biasP0,
            const float* __restrict__ lnscale,
            const float* __restrict__ lnbias,
            const float* __restrict__ jc,
            float* __restrict__ C) {
    extern __shared__ char sm[];
    const uint32_t sb = smem_u32(sm);
    float2* stats = (float2*)sm;      // 64 rows

    const int tid = threadIdx.x;
    const int lid = tid & 31;
    const int wid = tid >> 5;
    const int warp_m = wid & 1;
    const int warp_n = wid >> 1;
    const int qr = lid >> 2;
    const int qc = lid & 3;

    const int bm = blockIdx.x * 64;
    const int bn = blockIdx.y * 128;

    // B stage loader: 128 rows x 8 x 16B = 1024 tasks / 256 threads
    auto issueB = [&](int stage, int ch) {
        const uint32_t st = sb + SM_B + (uint32_t)stage * B_TILE_B;
        #pragma unroll
        for (int it = 0; it < 4; it++) {
            int idx = tid + it * 256;
            int row = idx >> 3, q8 = idx & 7;
            const __half* gb = Bn + (size_t)(bn + row) * KRED + ch * BK + q8 * 8;
            CP_ASYNC16(st + row * ROWB + q8 * 16, gb);
        }
        CP_COMMIT();
    };

    // h prefetch: row r0 = tid>>2, float4 col (tid&3)*4
    const int i4 = tid & 3;
    const int r0 = tid >> 2;
    auto loadH = [&](int ch, float4& v) {
        v = *(const float4*)(h + (size_t)(bm + r0) * DIM + ch * 16 + i4 * 4);
    };

    // A generation: row r0, 4 input dims -> 16 halves (32 B)
    auto genA = [&](int ch, int abuf, float4 v) {
        float4 j0 = __ldg((const float4*)jc);       // p1c, bb0, bb1, bb2
        float4 j1 = __ldg((const float4*)jc + 1);   // cc0, cc1, cc2, -
        float4 sc = *(const float4*)(lnscale + ch * 16 + i4 * 4);
        float4 bi = *(const float4*)(lnbias  + ch * 16 + i4 * 4);
        float2 st = stats[r0];
        float xv[4]  = {v.x, v.y, v.z, v.w};
        float scv[4] = {sc.x, sc.y, sc.z, sc.w};
        float biv[4] = {bi.x, bi.y, bi.z, bi.w};
        uint32_t oh[8];
        #pragma unroll
        for (int e = 0; e < 4; e++) {
            float x  = tanh_fast((xv[e] - st.x) * st.y * scv[e] + biv[e]);
            float P1 = j0.x * x;
            float P2 = j0.y * x * P1 - j1.x;
            float P3 = j0.z * x * P2 - j1.y * P1;
            float P4 = j0.w * x * P3 - j1.z * P2;
            __half2 h0 = __floats2half2_rn(P1, P2);
            __half2 h1 = __floats2half2_rn(P3, P4);
            oh[2 * e]     = *(uint32_t*)&h0;
            oh[2 * e + 1] = *(uint32_t*)&h1;
        }
        uint4* dst = (uint4*)(sm + SM_A + abuf * A_TILE_B + r0 * ROWB + i4 * 32);
        dst[0] = make_uint4(oh[0], oh[1], oh[2], oh[3]);
        dst[1] = make_uint4(oh[4], oh[5], oh[6], oh[7]);
    };

    // -------- prologue ------------------------------------------------------
    issueB(0, 0);
    issueB(1, 1);

    {   // LN stats: warp w -> rows w*8 .. w*8+7
        #pragma unroll 1
        for (int j = 0; j < 8; j++) {
            int row = wid * 8 + j;
            const float4* p = (const float4*)(h + (size_t)(bm + row) * DIM) + lid * 2;
            float4 u = p[0], v = p[1];
            float s  = u.x + u.y + u.z + u.w + v.x + v.y + v.z + v.w;
            float s2 = u.x*u.x + u.y*u.y + u.z*u.z + u.w*u.w
                     + v.x*v.x + v.y*v.y + v.z*v.z + v.w*v.w;
            #pragma unroll
            for (int off = 16; off; off >>= 1) {
                s  += __shfl_xor_sync(0xFFFFFFFFu, s,  off);
                s2 += __shfl_xor_sync(0xFFFFFFFFu, s2, off);
            }
            if (lid == 0) {
                float mu  = s * (1.0f / DIM);
                float var = s2 * (1.0f / DIM) - mu * mu;
                stats[row] = make_float2(mu, rsqrtf(var + LN_EPS));
            }
        }
    }
    __syncthreads();              // stats visible

    float4 hc, hn;
    loadH(0, hc);
    genA(0, 0, hc);
    loadH(1, hn);

    CP_WAIT1();                   // B(0) arrived
    __syncthreads();              // A(0) + B(0) visible

    // ldmatrix lane offsets
    const uint32_t a_loff =
        (uint32_t)((warp_m * 32 + (lid & 15)) * ROWB + ((lid >> 4) << 4));
    const uint32_t b_loff =
        (uint32_t)((warp_n * 32 + ((lid & 7) | ((lid >> 4) << 3))) * ROWB +
                   (((lid >> 3) & 1) << 4));

    float acc[2][4][4];
    #pragma unroll
    for (int mt = 0; mt < 2; mt++)
        #pragma unroll
        for (int nt = 0; nt < 4; nt++)
            #pragma unroll
            for (int j = 0; j < 4; j++) acc[mt][nt][j] = 0.0f;

    #pragma unroll 1
    for (int c = 0; c < NCHUNK; c++) {
        if (c + 2 < NCHUNK) issueB((c + 2) % 3, c + 2);
        else CP_COMMIT();

        const uint32_t stA = sb + SM_A + (uint32_t)(c & 1) * A_TILE_B;
        const uint32_t stB = sb + SM_B + (uint32_t)(c % 3) * B_TILE_B;

        #pragma unroll
        for (int ks = 0; ks < 4; ks++) {
            uint32_t af[2][4], bf[4][2];
            #pragma unroll
            for (int mt = 0; mt < 2; mt++)
                LDSM4(af[mt][0], af[mt][1], af[mt][2], af[mt][3],
                      stA + a_loff + (uint32_t)(mt * 16 * ROWB + ks * 32));
            #pragma unroll
            for (int p = 0; p < 2; p++)
                LDSM4(bf[2*p][0], bf[2*p][1], bf[2*p+1][0], bf[2*p+1][1],
                      stB + b_loff + (uint32_t)(p * 16 * ROWB + ks * 32));
            #pragma unroll
            for (int mt = 0; mt < 2; mt++)
                #pragma unroll
                for (int nt = 0; nt < 4; nt++)
                    mma_f16_16n8k16(acc[mt][nt], af[mt], bf[nt]);
        }

        if (c + 1 < NCHUNK) {
            genA(c + 1, (c + 1) & 1, hn);
            if (c + 2 < NCHUNK) loadH(c + 2, hn);
            CP_WAIT1();           // B(c+1) arrived
            __syncthreads();      // A(c+1) + B(c+1) visible
        }
    }

    // -------- epilogue: C = (acc + bias) / DIM ------------------------------
    const float inv = 1.0f / (float)DIM;
    const int re = bm + warp_m * 32 + qr;
    const int ce = bn + warp_n * 32 + qc * 2;
    #pragma unroll
    for (int mt = 0; mt < 2; mt++) {
        #pragma unroll
        for (int nt = 0; nt < 4; nt++) {
            int col = ce + nt * 8;
            float2 bv = *(const float2*)(biasP0 + col);
            int row = re + mt * 16;
            float2 o0, o1;
            o0.x = (acc[mt][nt][0] + bv.x) * inv;
            o0.y = (acc[mt][nt][1] + bv.y) * inv;
            o1.x = (acc[mt][nt][2] + bv.x) * inv;
            o1.y = (acc[mt][nt][3] + bv.y) * inv;
            *(float2*)(C + (size_t)row * DIM + col)       = o0;
            *(float2*)(C + (size_t)(row + 8) * DIM + col) = o1;
        }
    }
}

// ---------------------------------------------------------------------------
// Launch
// ---------------------------------------------------------------------------
extern "C" void kernel_launch(void* const* d_in, const int* in_sizes, int n_in,
                              void* d_out, int out_size) {
    const float* x        = (const float*)d_in[0];
    const float* coefs    = (const float*)d_in[1];
    const float* alphas   = (const float*)d_in[2];
    const float* ln_scale = (const float*)d_in[3];
    const float* ln_bias  = (const float*)d_in[4];
    float* out = (float*)d_out;

    float* hbuf; cudaGetSymbolAddress((void**)&hbuf, g_h);
    __half* Bn;  cudaGetSymbolAddress((void**)&Bn,   g_Bn);
    float* bias; cudaGetSymbolAddress((void**)&bias, g_bias);
    float* jc;   cudaGetSymbolAddress((void**)&jc,   g_jc);

    cudaFuncSetAttribute(fused_layer,
                         cudaFuncAttributeMaxDynamicSharedMemorySize,
                         SMEM_FUSED_BYTES);

    {
        int total = NLAYERS * DIM * KRED;
        build_Bn<<<(total + 255) / 256, 256>>>(coefs, Bn);
        build_bias<<<NLAYERS * DIM, 128>>>(coefs, alphas, bias, jc);
    }

    dim3 ggrid(BATCH / 64, DIM / 128);   // (128, 2) = 256 CTAs

    fused_layer<<<ggrid, 256, SMEM_FUSED_BYTES>>>(
        x, Bn, bias, ln_scale, ln_bias, jc, hbuf);

    fused_layer<<<ggrid, 256, SMEM_FUSED_BYTES>>>(
        hbuf, Bn + (size_t)DIM * KRED, bias + DIM,
        ln_scale + DIM, ln_bias + DIM, jc + 8, out);
}